// round 7
// baseline (speedup 1.0000x reference)
#include <cuda_runtime.h>
#include <math.h>
#include <stdint.h>

// Problem dims
#define BB 32
#define TT 512
#define II 128
#define HH 512
#define OO 128

// ---------------- device scratch (no allocs allowed) ----------------
__device__ float    g_pre [TT * HH * BB];   // [T][H][B] (reused pre0/pre1)
__device__ float    g_traj[TT * HH * BB];   // [T][H][B] (h1, then reused as h2)
__device__ float    g_tmp [TT * OO * BB];   // [T][O][B] (fc pre-transpose)
__device__ float    g_hping[4 * HH * BB];   // 2 ping-pong pairs (layer0, layer1)
__device__ unsigned g_root[1024];           // per-step root counters (512 per layer)
__device__ unsigned g_gcnt[8 * 1024];       // per-group counters: [g][layer*512 + t], 4KB stride between groups

// ---------------- init: zero counters + h0 buffers each replay ----------------
__global__ void init_kernel(unsigned* root, unsigned* gcnt, float* hping) {
    int i = blockIdx.x * blockDim.x + threadIdx.x;
    int stride = gridDim.x * blockDim.x;
    for (int e = i; e < 1024; e += stride) root[e] = 0u;
    for (int e = i; e < 8 * 1024; e += stride) gcnt[e] = 0u;
    for (int e = i; e < 4 * HH * BB; e += stride) hping[e] = 0.0f;
}

// ---------------- fp32 GEMM: C[t][j][b] = bias(j) + sum_k A(t,k,b)*W[j][k] ----------------
// grid: (N/128, T/2), block: 256. Tile 128j x 64n, microtile 8j x 4n. (R4-proven)
__global__ void __launch_bounds__(256)
gemm_pre_kernel(const float* __restrict__ A, const float* __restrict__ W,
                const float* __restrict__ bias1, const float* __restrict__ bias2,
                float* __restrict__ C,
                int K, long sAt, long sAk, long sAb, int N)
{
    __shared__ float Ws[32][132];  // [k][j] padded (128 j)
    __shared__ float As[32][68];   // [k][n] padded (64 n)

    const int t0  = blockIdx.y * 2;
    const int j0  = blockIdx.x * 128;
    const int tid = threadIdx.x;
    const int jg  = tid >> 4;      // 0..15 (8 j each)
    const int ng  = tid & 15;      // 0..15 (4 n each)

    float acc[8][4];
#pragma unroll
    for (int a = 0; a < 8; a++)
#pragma unroll
        for (int b = 0; b < 4; b++) acc[a][b] = 0.0f;

    for (int kt = 0; kt < K; kt += 32) {
        __syncthreads();
        // --- stage W tile transposed, coalesced ---
        {
            const int rowb = tid >> 3;        // 0..31
            const int k4   = (tid & 7) * 4;   // 0,4,..,28
#pragma unroll
            for (int i = 0; i < 4; i++) {
                const int row = i * 32 + rowb;
                float4 v = *(const float4*)&W[(size_t)(j0 + row) * K + kt + k4];
                Ws[k4 + 0][row] = v.x;
                Ws[k4 + 1][row] = v.y;
                Ws[k4 + 2][row] = v.z;
                Ws[k4 + 3][row] = v.w;
            }
        }
        // --- stage A tile: 32 k x 64 n ---
        if (sAb == 1) {   // b-contiguous (trajectory layout [t][k][b])
#pragma unroll
            for (int i = 0; i < 2; i++) {
                int f = tid + i * 256;
                int k  = f >> 4;
                int nq = (f & 15) * 4;
                int tloc = nq >> 5, b4 = nq & 31;
                float4 v = *(const float4*)&A[(size_t)(t0 + tloc) * sAt +
                                              (size_t)(kt + k) * sAk + b4];
                *(float4*)&As[k][nq] = v;
            }
        } else {          // k-contiguous (inputs layout [b][t][i])
#pragma unroll
            for (int i = 0; i < 2; i++) {
                int f = tid + i * 256;
                int n  = f >> 3;
                int kq = (f & 7) * 4;
                int tloc = n >> 5, b = n & 31;
                float4 v = *(const float4*)&A[(size_t)b * sAb +
                                              (size_t)(t0 + tloc) * sAt + kt + kq];
                As[kq + 0][n] = v.x;
                As[kq + 1][n] = v.y;
                As[kq + 2][n] = v.z;
                As[kq + 3][n] = v.w;
            }
        }
        __syncthreads();
#pragma unroll
        for (int k = 0; k < 32; k++) {
            const float4 w0 = *(const float4*)&Ws[k][jg * 8];
            const float4 w1 = *(const float4*)&Ws[k][jg * 8 + 4];
            const float4 a  = *(const float4*)&As[k][ng * 4];
            acc[0][0] += w0.x * a.x; acc[0][1] += w0.x * a.y; acc[0][2] += w0.x * a.z; acc[0][3] += w0.x * a.w;
            acc[1][0] += w0.y * a.x; acc[1][1] += w0.y * a.y; acc[1][2] += w0.y * a.z; acc[1][3] += w0.y * a.w;
            acc[2][0] += w0.z * a.x; acc[2][1] += w0.z * a.y; acc[2][2] += w0.z * a.z; acc[2][3] += w0.z * a.w;
            acc[3][0] += w0.w * a.x; acc[3][1] += w0.w * a.y; acc[3][2] += w0.w * a.z; acc[3][3] += w0.w * a.w;
            acc[4][0] += w1.x * a.x; acc[4][1] += w1.x * a.y; acc[4][2] += w1.x * a.z; acc[4][3] += w1.x * a.w;
            acc[5][0] += w1.y * a.x; acc[5][1] += w1.y * a.y; acc[5][2] += w1.y * a.z; acc[5][3] += w1.y * a.w;
            acc[6][0] += w1.z * a.x; acc[6][1] += w1.z * a.y; acc[6][2] += w1.z * a.z; acc[6][3] += w1.z * a.w;
            acc[7][0] += w1.w * a.x; acc[7][1] += w1.w * a.y; acc[7][2] += w1.w * a.z; acc[7][3] += w1.w * a.w;
        }
    }

    const int tloc = ng >> 3;
    const int b4   = (ng & 7) * 4;
    float* Crow = &C[(size_t)(t0 + tloc) * N * BB + b4];
#pragma unroll
    for (int ji = 0; ji < 8; ji++) {
        int j = j0 + jg * 8 + ji;
        float bb = bias1 ? bias1[j] : 0.0f;
        if (bias2) bb += bias2[j];
        float4 o = make_float4(acc[ji][0] + bb, acc[ji][1] + bb, acc[ji][2] + bb, acc[ji][3] + bb);
        *(float4*)&Crow[(size_t)j * BB] = o;
    }
}

// ---------------- persistent recurrence layer ----------------
// grid: 128 CTAs (co-resident), block: 128 threads. CTA owns 4 hidden columns.
// Grid barrier per step: TWO-LEVEL. 8 groups of 16 CTAs; group counters live in
// 4KB-strided regions (distinct L2 lines -> parallel atomic service); 16th
// arriver per group bumps the root; all spin on root==8.
__global__ void __launch_bounds__(128)
rnn_layer_kernel(const float* __restrict__ pre, float* __restrict__ traj,
                 const float* __restrict__ W,
                 float* buf0, float* buf1,
                 unsigned* root, unsigned* gcnt)   // gcnt: [g*1024 + t] (layer offset pre-applied)
{
    __shared__ float Wt[16][32][4];   // [kk][kseg][jj]  8KB
    __shared__ float ps[32][132];     // partials [kseg][out], padded

    const int tid  = threadIdx.x;
    const int j0   = blockIdx.x * 4;
    const int gid  = blockIdx.x >> 4; // 8 groups of 16 CTAs
    const int bg   = tid & 3;
    const int kseg = tid >> 2;        // 0..31
    const int b0   = bg * 8;

    // preload W slice: Wt[kk][ks][jj] = W[(j0+jj)*H + ks*16 + kk]
    for (int e = tid; e < 2048; e += 128) {
        int jj = e & 3;
        int ks = (e >> 2) & 31;
        int kk = e >> 7;
        Wt[kk][ks][jj] = W[(size_t)(j0 + jj) * HH + ks * 16 + kk];
    }
    __syncthreads();

    const int out_b  = tid >> 2;      // output this thread finalizes
    const int out_jj = tid & 3;

    for (int t = 0; t < TT; t++) {
        const float* hb = (t & 1) ? buf1 : buf0;
        float*       hn = (t & 1) ? buf0 : buf1;

        const float preval = pre[(size_t)t * (HH * BB) + (size_t)(j0 + out_jj) * BB + out_b];

        float acc[8][4];
#pragma unroll
        for (int a = 0; a < 8; a++)
#pragma unroll
            for (int b = 0; b < 4; b++) acc[a][b] = 0.0f;

#pragma unroll
        for (int kk = 0; kk < 16; kk++) {
            const int k = kseg * 16 + kk;
            const float4 w  = *(const float4*)&Wt[kk][kseg][0];
            const float4 hA = __ldcg((const float4*)(hb + (k << 5) + b0));
            const float4 hB = __ldcg((const float4*)(hb + (k << 5) + b0 + 4));
            acc[0][0] += hA.x * w.x; acc[0][1] += hA.x * w.y; acc[0][2] += hA.x * w.z; acc[0][3] += hA.x * w.w;
            acc[1][0] += hA.y * w.x; acc[1][1] += hA.y * w.y; acc[1][2] += hA.y * w.z; acc[1][3] += hA.y * w.w;
            acc[2][0] += hA.z * w.x; acc[2][1] += hA.z * w.y; acc[2][2] += hA.z * w.z; acc[2][3] += hA.z * w.w;
            acc[3][0] += hA.w * w.x; acc[3][1] += hA.w * w.y; acc[3][2] += hA.w * w.z; acc[3][3] += hA.w * w.w;
            acc[4][0] += hB.x * w.x; acc[4][1] += hB.x * w.y; acc[4][2] += hB.x * w.z; acc[4][3] += hB.x * w.w;
            acc[5][0] += hB.y * w.x; acc[5][1] += hB.y * w.y; acc[5][2] += hB.y * w.z; acc[5][3] += hB.y * w.w;
            acc[6][0] += hB.z * w.x; acc[6][1] += hB.z * w.y; acc[6][2] += hB.z * w.z; acc[6][3] += hB.z * w.w;
            acc[7][0] += hB.w * w.x; acc[7][1] += hB.w * w.y; acc[7][2] += hB.w * w.z; acc[7][3] += hB.w * w.w;
        }

        // dump partials: out index = b*4 + jj
#pragma unroll
        for (int bi = 0; bi < 8; bi++) {
            *(float4*)&ps[kseg][(bg * 8 + bi) * 4] =
                make_float4(acc[bi][0], acc[bi][1], acc[bi][2], acc[bi][3]);
        }
        __syncthreads();

        // reduce 32 k-segments for output 'tid' (4-way split chains)
        float s0 = 0.f, s1 = 0.f, s2 = 0.f, s3 = 0.f;
#pragma unroll
        for (int ss = 0; ss < 32; ss += 4) {
            s0 += ps[ss + 0][tid];
            s1 += ps[ss + 1][tid];
            s2 += ps[ss + 2][tid];
            s3 += ps[ss + 3][tid];
        }
        const float val = tanhf(preval + (s0 + s1) + (s2 + s3));
        const int jdx = j0 + out_jj;
        hn[(size_t)jdx * BB + out_b] = val;
        traj[(size_t)t * (HH * BB) + (size_t)jdx * BB + out_b] = val;

        __threadfence();
        __syncthreads();   // all stores + fences done; also guards ps reuse

        if (tid == 0) {
            unsigned a = atomicAdd(&gcnt[gid * 1024 + t], 1u);
            if (a == 15u) {                 // 16th arrival in this group
                __threadfence();            // order before root publish
                atomicAdd(&root[t], 1u);
            }
            volatile unsigned* p = &root[t];
            while (*p < 8u) { __nanosleep(40); }
        }
        __syncthreads();
    }
}

// ---------------- transpose: g_tmp [T][O][B] -> out [B][O][T] ----------------
__global__ void transpose_kernel(const float* __restrict__ tmp, float* __restrict__ out)
{
    __shared__ float s[32][33];
    const int t0 = blockIdx.x * 32;
    const int o  = blockIdx.y;
    const int tx = threadIdx.x;   // 32
    const int ty = threadIdx.y;   // 8
#pragma unroll
    for (int i = 0; i < 4; i++) {
        int tt = t0 + ty + i * 8;
        s[ty + i * 8][tx] = tmp[(size_t)tt * (OO * BB) + (size_t)o * BB + tx];
    }
    __syncthreads();
#pragma unroll
    for (int i = 0; i < 4; i++) {
        int b = ty + i * 8;
        out[(size_t)b * (OO * TT) + (size_t)o * TT + t0 + tx] = s[tx][b];
    }
}

// ---------------- launch ----------------
extern "C" void kernel_launch(void* const* d_in, const int* in_sizes, int n_in,
                              void* d_out, int out_size)
{
    const float* inputs = (const float*)d_in[0];
    const float* W_ih0  = (const float*)d_in[1];
    const float* W_hh0  = (const float*)d_in[2];
    const float* b_ih0  = (const float*)d_in[3];
    const float* b_hh0  = (const float*)d_in[4];
    const float* W_ih1  = (const float*)d_in[5];
    const float* W_hh1  = (const float*)d_in[6];
    const float* b_ih1  = (const float*)d_in[7];
    const float* b_hh1  = (const float*)d_in[8];
    const float* W_fc   = (const float*)d_in[9];
    const float* b_fc   = (const float*)d_in[10];

    float *pre, *traj, *tmp, *hping;
    unsigned *root, *gcnt;
    cudaGetSymbolAddress((void**)&pre,   g_pre);
    cudaGetSymbolAddress((void**)&traj,  g_traj);
    cudaGetSymbolAddress((void**)&tmp,   g_tmp);
    cudaGetSymbolAddress((void**)&hping, g_hping);
    cudaGetSymbolAddress((void**)&root,  g_root);
    cudaGetSymbolAddress((void**)&gcnt,  g_gcnt);

    init_kernel<<<64, 256>>>(root, gcnt, hping);

    // pre0[t][j][b] = inputs[b][t][:] . W_ih0[j][:] + b_ih0[j] + b_hh0[j]
    gemm_pre_kernel<<<dim3(4, TT / 2), 256>>>(inputs, W_ih0, b_ih0, b_hh0, pre,
                                              II, (long)II, 1L, (long)TT * II, HH);

    // layer 0 recurrence -> h1 trajectory
    rnn_layer_kernel<<<128, 128>>>(pre, traj, W_hh0,
                                   hping, hping + HH * BB,
                                   root, gcnt);

    // pre1[t][j][b] = h1[t][:][b] . W_ih1[j][:] + b_ih1[j] + b_hh1[j]
    gemm_pre_kernel<<<dim3(4, TT / 2), 256>>>(traj, W_ih1, b_ih1, b_hh1, pre,
                                              HH, (long)HH * BB, (long)BB, 1L, HH);

    // layer 1 recurrence -> h2 trajectory (reuses g_traj)
    rnn_layer_kernel<<<128, 128>>>(pre, traj, W_hh1,
                                   hping + 2 * HH * BB, hping + 3 * HH * BB,
                                   root + 512, gcnt + 512);

    // fc: tmp[t][o][b] = h2[t][:][b] . W_fc[o][:] + b_fc[o]
    gemm_pre_kernel<<<dim3(1, TT / 2), 256>>>(traj, W_fc, b_fc, nullptr, tmp,
                                              HH, (long)HH * BB, (long)BB, 1L, OO);

    // out[b][o][t] = tmp[t][o][b]
    transpose_kernel<<<dim3(16, OO), dim3(32, 8)>>>(tmp, (float*)d_out);
}

// round 9
// speedup vs baseline: 1.0939x; 1.0939x over previous
#include <cuda_runtime.h>
#include <math.h>
#include <stdint.h>

// Problem dims
#define BB 32
#define TT 512
#define II 128
#define HH 512
#define OO 128
#define HB (HH * BB)   // 16384 floats per timestep slab

// ---------------- device scratch (no allocs allowed) ----------------
__device__ float    g_pre [TT * HH * BB];          // [T][H][B] pre0
__device__ float    g_h1  [(TT + 1) * HH * BB];    // h1 trajectory, slot-shifted: h1[t] at slot t+1, slot0 = 0
__device__ float    g_h2  [(TT + 1) * HH * BB];    // h2 trajectory, slot-shifted
__device__ float    g_tmp [TT * OO * BB];          // [T][O][B] fc pre-transpose
__device__ unsigned g_counters[1024];              // per-fused-step barrier counters

// ---------------- init: zero counters + zero slots each replay ----------------
__global__ void init_kernel(unsigned* counters, float* h1, float* h2) {
    int i = blockIdx.x * blockDim.x + threadIdx.x;
    int stride = gridDim.x * blockDim.x;
    for (int e = i; e < 1024; e += stride) counters[e] = 0u;
    for (int e = i; e < HB; e += stride) { h1[e] = 0.0f; h2[e] = 0.0f; }
}

// ---------------- fp32 GEMM: C[t][j][b] = bias(j) + sum_k A(t,k,b)*W[j][k] ----------------
// grid: (N/128, T/2), block: 256. Tile 128j x 64n, microtile 8j x 4n. (R4-proven)
__global__ void __launch_bounds__(256)
gemm_pre_kernel(const float* __restrict__ A, const float* __restrict__ W,
                const float* __restrict__ bias1, const float* __restrict__ bias2,
                float* __restrict__ C,
                int K, long sAt, long sAk, long sAb, int N)
{
    __shared__ float Ws[32][132];  // [k][j] padded (128 j)
    __shared__ float As[32][68];   // [k][n] padded (64 n)

    const int t0  = blockIdx.y * 2;
    const int j0  = blockIdx.x * 128;
    const int tid = threadIdx.x;
    const int jg  = tid >> 4;      // 0..15 (8 j each)
    const int ng  = tid & 15;      // 0..15 (4 n each)

    float acc[8][4];
#pragma unroll
    for (int a = 0; a < 8; a++)
#pragma unroll
        for (int b = 0; b < 4; b++) acc[a][b] = 0.0f;

    for (int kt = 0; kt < K; kt += 32) {
        __syncthreads();
        {
            const int rowb = tid >> 3;
            const int k4   = (tid & 7) * 4;
#pragma unroll
            for (int i = 0; i < 4; i++) {
                const int row = i * 32 + rowb;
                float4 v = *(const float4*)&W[(size_t)(j0 + row) * K + kt + k4];
                Ws[k4 + 0][row] = v.x;
                Ws[k4 + 1][row] = v.y;
                Ws[k4 + 2][row] = v.z;
                Ws[k4 + 3][row] = v.w;
            }
        }
        if (sAb == 1) {   // b-contiguous (trajectory layout [t][k][b])
#pragma unroll
            for (int i = 0; i < 2; i++) {
                int f = tid + i * 256;
                int k  = f >> 4;
                int nq = (f & 15) * 4;
                int tloc = nq >> 5, b4 = nq & 31;
                float4 v = *(const float4*)&A[(size_t)(t0 + tloc) * sAt +
                                              (size_t)(kt + k) * sAk + b4];
                *(float4*)&As[k][nq] = v;
            }
        } else {          // k-contiguous (inputs layout [b][t][i])
#pragma unroll
            for (int i = 0; i < 2; i++) {
                int f = tid + i * 256;
                int n  = f >> 3;
                int kq = (f & 7) * 4;
                int tloc = n >> 5, b = n & 31;
                float4 v = *(const float4*)&A[(size_t)b * sAb +
                                              (size_t)(t0 + tloc) * sAt + kt + kq];
                As[kq + 0][n] = v.x;
                As[kq + 1][n] = v.y;
                As[kq + 2][n] = v.z;
                As[kq + 3][n] = v.w;
            }
        }
        __syncthreads();
#pragma unroll
        for (int k = 0; k < 32; k++) {
            const float4 w0 = *(const float4*)&Ws[k][jg * 8];
            const float4 w1 = *(const float4*)&Ws[k][jg * 8 + 4];
            const float4 a  = *(const float4*)&As[k][ng * 4];
            acc[0][0] += w0.x * a.x; acc[0][1] += w0.x * a.y; acc[0][2] += w0.x * a.z; acc[0][3] += w0.x * a.w;
            acc[1][0] += w0.y * a.x; acc[1][1] += w0.y * a.y; acc[1][2] += w0.y * a.z; acc[1][3] += w0.y * a.w;
            acc[2][0] += w0.z * a.x; acc[2][1] += w0.z * a.y; acc[2][2] += w0.z * a.z; acc[2][3] += w0.z * a.w;
            acc[3][0] += w0.w * a.x; acc[3][1] += w0.w * a.y; acc[3][2] += w0.w * a.z; acc[3][3] += w0.w * a.w;
            acc[4][0] += w1.x * a.x; acc[4][1] += w1.x * a.y; acc[4][2] += w1.x * a.z; acc[4][3] += w1.x * a.w;
            acc[5][0] += w1.y * a.x; acc[5][1] += w1.y * a.y; acc[5][2] += w1.y * a.z; acc[5][3] += w1.y * a.w;
            acc[6][0] += w1.z * a.x; acc[6][1] += w1.z * a.y; acc[6][2] += w1.z * a.z; acc[6][3] += w1.z * a.w;
            acc[7][0] += w1.w * a.x; acc[7][1] += w1.w * a.y; acc[7][2] += w1.w * a.z; acc[7][3] += w1.w * a.w;
        }
    }

    const int tloc = ng >> 3;
    const int b4   = (ng & 7) * 4;
    float* Crow = &C[(size_t)(t0 + tloc) * N * BB + b4];
#pragma unroll
    for (int ji = 0; ji < 8; ji++) {
        int j = j0 + jg * 8 + ji;
        float bb = bias1 ? bias1[j] : 0.0f;
        if (bias2) bb += bias2[j];
        float4 o = make_float4(acc[ji][0] + bb, acc[ji][1] + bb, acc[ji][2] + bb, acc[ji][3] + bb);
        *(float4*)&Crow[(size_t)j * BB] = o;
    }
}

// ---------------- fused two-layer wavefront recurrence ----------------
// grid: 128 CTAs (co-resident), block: 128 threads. Each CTA owns 4 columns of
// BOTH layers. Fused step s: compute h1[s] (layer0) and h2[s-1] (layer1).
// h1[s-1] is read ONCE and feeds both W_hh0 (layer0) and W_ih1 (layer1).
// 513 grid barriers total (vs 1024 unfused). Barrier = R6-proven flat pattern.
__device__ __forceinline__ void fmarow(float4& acc, float hv, const float4& wv) {
    acc.x += hv * wv.x;
    acc.y += hv * wv.y;
    acc.z += hv * wv.z;
    acc.w += hv * wv.w;
}

__global__ void __launch_bounds__(128)
fused_rnn_kernel(const float* __restrict__ pre,
                 float* __restrict__ h1traj, float* __restrict__ h2traj,
                 const float* __restrict__ Whh0,
                 const float* __restrict__ Wih1, const float* __restrict__ Whh1,
                 const float* __restrict__ b_ih1, const float* __restrict__ b_hh1,
                 unsigned* counters)
{
    __shared__ float Wt0 [16][32][4];   // W_hh0 slice  8KB
    __shared__ float Wt1i[16][32][4];   // W_ih1 slice  8KB
    __shared__ float Wt1h[16][32][4];   // W_hh1 slice  8KB
    __shared__ float ps[32][132];       // partials [kseg][out], padded ~17KB (reused for both phases)

    const int tid  = threadIdx.x;
    const int j0   = blockIdx.x * 4;
    const int bg   = tid & 3;
    const int kseg = tid >> 2;        // 0..31
    const int b0   = bg * 8;

    // preload the three W slices: Wt[kk][ks][jj] = W[(j0+jj)*H + ks*16 + kk]
    for (int e = tid; e < 2048; e += 128) {
        int jj = e & 3;
        int ks = (e >> 2) & 31;
        int kk = e >> 7;
        size_t widx = (size_t)(j0 + jj) * HH + ks * 16 + kk;
        Wt0 [kk][ks][jj] = Whh0[widx];
        Wt1i[kk][ks][jj] = Wih1[widx];
        Wt1h[kk][ks][jj] = Whh1[widx];
    }
    __syncthreads();

    const int out_b  = tid >> 2;      // output this thread finalizes
    const int out_jj = tid & 3;
    const int jdx    = j0 + out_jj;
    const float bias1v = b_ih1[jdx] + b_hh1[jdx];

    for (int s = 0; s <= TT; s++) {
        const bool l0 = (s < TT);     // layer0 computes h1[s]
        const bool l1 = (s >= 1);     // layer1 computes h2[s-1]
        const int  tp = l0 ? s : (TT - 1);             // clamped pre0 timestep
        const int  h2slot = (s >= 1) ? (s - 1) : 0;    // h2[s-2] slot (clamped; slot0 = zeros)

        const float* h1p = h1traj + (size_t)s * HB + kseg * 16 * BB + b0;        // h1[s-1]
        const float* h2p = h2traj + (size_t)h2slot * HB + kseg * 16 * BB + b0;   // h2[s-2]

        const float preval = pre[(size_t)tp * HB + (size_t)jdx * BB + out_b];

        float4 acc0[8], acc1[8];
#pragma unroll
        for (int a = 0; a < 8; a++) {
            acc0[a] = make_float4(0.f, 0.f, 0.f, 0.f);
            acc1[a] = make_float4(0.f, 0.f, 0.f, 0.f);
        }

#pragma unroll
        for (int kk = 0; kk < 16; kk++) {
            const float4 w0 = *(const float4*)&Wt0 [kk][kseg][0];
            const float4 wi = *(const float4*)&Wt1i[kk][kseg][0];
            const float4 wh = *(const float4*)&Wt1h[kk][kseg][0];
            const float4 aA = __ldcg((const float4*)(h1p + kk * BB));
            const float4 aB = __ldcg((const float4*)(h1p + kk * BB + 4));
            const float4 cA = __ldcg((const float4*)(h2p + kk * BB));
            const float4 cB = __ldcg((const float4*)(h2p + kk * BB + 4));
            // layer0: h1 x W_hh0
            fmarow(acc0[0], aA.x, w0); fmarow(acc0[1], aA.y, w0);
            fmarow(acc0[2], aA.z, w0); fmarow(acc0[3], aA.w, w0);
            fmarow(acc0[4], aB.x, w0); fmarow(acc0[5], aB.y, w0);
            fmarow(acc0[6], aB.z, w0); fmarow(acc0[7], aB.w, w0);
            // layer1: h1 x W_ih1
            fmarow(acc1[0], aA.x, wi); fmarow(acc1[1], aA.y, wi);
            fmarow(acc1[2], aA.z, wi); fmarow(acc1[3], aA.w, wi);
            fmarow(acc1[4], aB.x, wi); fmarow(acc1[5], aB.y, wi);
            fmarow(acc1[6], aB.z, wi); fmarow(acc1[7], aB.w, wi);
            // layer1: h2 x W_hh1
            fmarow(acc1[0], cA.x, wh); fmarow(acc1[1], cA.y, wh);
            fmarow(acc1[2], cA.z, wh); fmarow(acc1[3], cA.w, wh);
            fmarow(acc1[4], cB.x, wh); fmarow(acc1[5], cB.y, wh);
            fmarow(acc1[6], cB.z, wh); fmarow(acc1[7], cB.w, wh);
        }

        // ---- phase 0: reduce layer0, write h1[s] ----
#pragma unroll
        for (int bi = 0; bi < 8; bi++)
            *(float4*)&ps[kseg][(bg * 8 + bi) * 4] = acc0[bi];
        __syncthreads();
        {
            float s0 = 0.f, s1 = 0.f, s2 = 0.f, s3 = 0.f;
#pragma unroll
            for (int ss = 0; ss < 32; ss += 4) {
                s0 += ps[ss + 0][tid];
                s1 += ps[ss + 1][tid];
                s2 += ps[ss + 2][tid];
                s3 += ps[ss + 3][tid];
            }
            if (l0) {
                const float val = tanhf(preval + (s0 + s1) + (s2 + s3));
                h1traj[(size_t)(s + 1) * HB + (size_t)jdx * BB + out_b] = val;
            }
        }
        __syncthreads();   // ps reuse guard

        // ---- phase 1: reduce layer1, write h2[s-1] ----
#pragma unroll
        for (int bi = 0; bi < 8; bi++)
            *(float4*)&ps[kseg][(bg * 8 + bi) * 4] = acc1[bi];
        __syncthreads();
        {
            float s0 = 0.f, s1 = 0.f, s2 = 0.f, s3 = 0.f;
#pragma unroll
            for (int ss = 0; ss < 32; ss += 4) {
                s0 += ps[ss + 0][tid];
                s1 += ps[ss + 1][tid];
                s2 += ps[ss + 2][tid];
                s3 += ps[ss + 3][tid];
            }
            if (l1) {
                const float val = tanhf(bias1v + (s0 + s1) + (s2 + s3));
                h2traj[(size_t)s * HB + (size_t)jdx * BB + out_b] = val;   // h2[s-1] at slot s
            }
        }

        // ---- grid barrier (R6-proven flat pattern) ----
        __threadfence();
        __syncthreads();   // all stores + fences done; also guards ps reuse

        if (tid == 0) {
            unsigned arrived = atomicAdd(&counters[s], 1u) + 1u;
            if (arrived < 128u) {
                volatile unsigned* p = &counters[s];
                while (*p < 128u) { __nanosleep(40); }
            }
        }
        __syncthreads();
    }
}

// ---------------- transpose: g_tmp [T][O][B] -> out [B][O][T] ----------------
__global__ void transpose_kernel(const float* __restrict__ tmp, float* __restrict__ out)
{
    __shared__ float s[32][33];
    const int t0 = blockIdx.x * 32;
    const int o  = blockIdx.y;
    const int tx = threadIdx.x;   // 32
    const int ty = threadIdx.y;   // 8
#pragma unroll
    for (int i = 0; i < 4; i++) {
        int tt = t0 + ty + i * 8;
        s[ty + i * 8][tx] = tmp[(size_t)tt * (OO * BB) + (size_t)o * BB + tx];
    }
    __syncthreads();
#pragma unroll
    for (int i = 0; i < 4; i++) {
        int b = ty + i * 8;
        out[(size_t)b * (OO * TT) + (size_t)o * TT + t0 + tx] = s[tx][b];
    }
}

// ---------------- launch ----------------
extern "C" void kernel_launch(void* const* d_in, const int* in_sizes, int n_in,
                              void* d_out, int out_size)
{
    const float* inputs = (const float*)d_in[0];
    const float* W_ih0  = (const float*)d_in[1];
    const float* W_hh0  = (const float*)d_in[2];
    const float* b_ih0  = (const float*)d_in[3];
    const float* b_hh0  = (const float*)d_in[4];
    const float* W_ih1  = (const float*)d_in[5];
    const float* W_hh1  = (const float*)d_in[6];
    const float* b_ih1  = (const float*)d_in[7];
    const float* b_hh1  = (const float*)d_in[8];
    const float* W_fc   = (const float*)d_in[9];
    const float* b_fc   = (const float*)d_in[10];

    float *pre, *h1, *h2, *tmp;
    unsigned* counters;
    cudaGetSymbolAddress((void**)&pre,      g_pre);
    cudaGetSymbolAddress((void**)&h1,       g_h1);
    cudaGetSymbolAddress((void**)&h2,       g_h2);
    cudaGetSymbolAddress((void**)&tmp,      g_tmp);
    cudaGetSymbolAddress((void**)&counters, g_counters);

    init_kernel<<<64, 256>>>(counters, h1, h2);

    // pre0[t][j][b] = inputs[b][t][:] . W_ih0[j][:] + b_ih0[j] + b_hh0[j]
    gemm_pre_kernel<<<dim3(4, TT / 2), 256>>>(inputs, W_ih0, b_ih0, b_hh0, pre,
                                              II, (long)II, 1L, (long)TT * II, HH);

    // fused two-layer wavefront: writes h1 traj (slots 1..T) and h2 traj (slots 1..T)
    fused_rnn_kernel<<<128, 128>>>(pre, h1, h2, W_hh0, W_ih1, W_hh1,
                                   b_ih1, b_hh1, counters);

    // fc: tmp[t][o][b] = h2[t][:][b] . W_fc[o][:] + b_fc[o]   (h2[t] at slot t+1)
    gemm_pre_kernel<<<dim3(1, TT / 2), 256>>>(h2 + HB, W_fc, b_fc, nullptr, tmp,
                                              HH, (long)HB, (long)BB, 1L, OO);

    // out[b][o][t] = tmp[t][o][b]
    transpose_kernel<<<dim3(16, OO), dim3(32, 8)>>>(tmp, (float*)d_out);
}

// round 10
// speedup vs baseline: 1.1857x; 1.0840x over previous
#include <cuda_runtime.h>
#include <math.h>
#include <stdint.h>

// Problem dims
#define BB 32
#define TT 512
#define II 128
#define HH 512
#define OO 128

// ---------------- device scratch (no allocs allowed) ----------------
__device__ float    g_pre [TT * HH * BB];   // [T][H][B] (reused pre0/pre1)
__device__ float    g_traj[TT * HH * BB];   // [T][H][B] (h1, then reused as h2)
__device__ float    g_tmp [TT * OO * BB];   // [T][O][B] (fc pre-transpose)
__device__ float    g_hping[4 * HH * BB];   // 2 ping-pong pairs (layer0, layer1)
__device__ unsigned g_counters[1024];       // per-step barrier counters (512 per layer)

// ---------------- init: zero counters + h0 buffers each replay ----------------
__global__ void init_kernel(unsigned* counters, float* hping) {
    int i = blockIdx.x * blockDim.x + threadIdx.x;
    int stride = gridDim.x * blockDim.x;
    for (int e = i; e < 1024; e += stride) counters[e] = 0u;
    for (int e = i; e < 4 * HH * BB; e += stride) hping[e] = 0.0f;
}

// ---------------- fp32 GEMM: C[t][j][b] = bias(j) + sum_k A(t,k,b)*W[j][k] ----------------
// grid: (N/128, T/2), block: 256. Tile 128j x 64n, microtile 8j x 4n. (R4-proven)
__global__ void __launch_bounds__(256)
gemm_pre_kernel(const float* __restrict__ A, const float* __restrict__ W,
                const float* __restrict__ bias1, const float* __restrict__ bias2,
                float* __restrict__ C,
                int K, long sAt, long sAk, long sAb, int N)
{
    __shared__ float Ws[32][132];  // [k][j] padded (128 j)
    __shared__ float As[32][68];   // [k][n] padded (64 n)

    const int t0  = blockIdx.y * 2;
    const int j0  = blockIdx.x * 128;
    const int tid = threadIdx.x;
    const int jg  = tid >> 4;      // 0..15 (8 j each)
    const int ng  = tid & 15;      // 0..15 (4 n each)

    float acc[8][4];
#pragma unroll
    for (int a = 0; a < 8; a++)
#pragma unroll
        for (int b = 0; b < 4; b++) acc[a][b] = 0.0f;

    for (int kt = 0; kt < K; kt += 32) {
        __syncthreads();
        {
            const int rowb = tid >> 3;
            const int k4   = (tid & 7) * 4;
#pragma unroll
            for (int i = 0; i < 4; i++) {
                const int row = i * 32 + rowb;
                float4 v = *(const float4*)&W[(size_t)(j0 + row) * K + kt + k4];
                Ws[k4 + 0][row] = v.x;
                Ws[k4 + 1][row] = v.y;
                Ws[k4 + 2][row] = v.z;
                Ws[k4 + 3][row] = v.w;
            }
        }
        if (sAb == 1) {   // b-contiguous (trajectory layout [t][k][b])
#pragma unroll
            for (int i = 0; i < 2; i++) {
                int f = tid + i * 256;
                int k  = f >> 4;
                int nq = (f & 15) * 4;
                int tloc = nq >> 5, b4 = nq & 31;
                float4 v = *(const float4*)&A[(size_t)(t0 + tloc) * sAt +
                                              (size_t)(kt + k) * sAk + b4];
                *(float4*)&As[k][nq] = v;
            }
        } else {          // k-contiguous (inputs layout [b][t][i])
#pragma unroll
            for (int i = 0; i < 2; i++) {
                int f = tid + i * 256;
                int n  = f >> 3;
                int kq = (f & 7) * 4;
                int tloc = n >> 5, b = n & 31;
                float4 v = *(const float4*)&A[(size_t)b * sAb +
                                              (size_t)(t0 + tloc) * sAt + kt + kq];
                As[kq + 0][n] = v.x;
                As[kq + 1][n] = v.y;
                As[kq + 2][n] = v.z;
                As[kq + 3][n] = v.w;
            }
        }
        __syncthreads();
#pragma unroll
        for (int k = 0; k < 32; k++) {
            const float4 w0 = *(const float4*)&Ws[k][jg * 8];
            const float4 w1 = *(const float4*)&Ws[k][jg * 8 + 4];
            const float4 a  = *(const float4*)&As[k][ng * 4];
            acc[0][0] += w0.x * a.x; acc[0][1] += w0.x * a.y; acc[0][2] += w0.x * a.z; acc[0][3] += w0.x * a.w;
            acc[1][0] += w0.y * a.x; acc[1][1] += w0.y * a.y; acc[1][2] += w0.y * a.z; acc[1][3] += w0.y * a.w;
            acc[2][0] += w0.z * a.x; acc[2][1] += w0.z * a.y; acc[2][2] += w0.z * a.z; acc[2][3] += w0.z * a.w;
            acc[3][0] += w0.w * a.x; acc[3][1] += w0.w * a.y; acc[3][2] += w0.w * a.z; acc[3][3] += w0.w * a.w;
            acc[4][0] += w1.x * a.x; acc[4][1] += w1.x * a.y; acc[4][2] += w1.x * a.z; acc[4][3] += w1.x * a.w;
            acc[5][0] += w1.y * a.x; acc[5][1] += w1.y * a.y; acc[5][2] += w1.y * a.z; acc[5][3] += w1.y * a.w;
            acc[6][0] += w1.z * a.x; acc[6][1] += w1.z * a.y; acc[6][2] += w1.z * a.z; acc[6][3] += w1.z * a.w;
            acc[7][0] += w1.w * a.x; acc[7][1] += w1.w * a.y; acc[7][2] += w1.w * a.z; acc[7][3] += w1.w * a.w;
        }
    }

    const int tloc = ng >> 3;
    const int b4   = (ng & 7) * 4;
    float* Crow = &C[(size_t)(t0 + tloc) * N * BB + b4];
#pragma unroll
    for (int ji = 0; ji < 8; ji++) {
        int j = j0 + jg * 8 + ji;
        float bb = bias1 ? bias1[j] : 0.0f;
        if (bias2) bb += bias2[j];
        float4 o = make_float4(acc[ji][0] + bb, acc[ji][1] + bb, acc[ji][2] + bb, acc[ji][3] + bb);
        *(float4*)&Crow[(size_t)j * BB] = o;
    }
}

// ---------------- persistent recurrence layer ----------------
// grid: 128 CTAs (co-resident), block: 256 threads (2 warps/SMSP for latency
// hiding). CTA owns 4 hidden columns; thread = (kseg 0..31, bg 0..7), covers
// 16 k x 4 b x 4 j. Barrier: R6-proven flat pattern (threadfence + atomicAdd
// return + volatile spin + nanosleep).
__global__ void __launch_bounds__(256)
rnn_layer_kernel(const float* __restrict__ pre, float* __restrict__ traj,
                 const float* __restrict__ W,
                 float* buf0, float* buf1, unsigned* counters)
{
    __shared__ float Wt[16][32][4];   // [kk][kseg][jj]  8KB
    __shared__ float ps[32][132];     // partials [kseg][out] padded  ~17KB

    const int tid  = threadIdx.x;
    const int j0   = blockIdx.x * 4;
    const int kseg = tid >> 3;        // 0..31 (16 k each)
    const int bg   = tid & 7;         // 0..7  (4 b each)
    const int b0   = bg * 4;

    // preload W slice: Wt[kk][ks][jj] = W[(j0+jj)*H + ks*16 + kk]
    for (int e = tid; e < 2048; e += 256) {
        int jj = e & 3;
        int ks = (e >> 2) & 31;
        int kk = e >> 7;
        Wt[kk][ks][jj] = W[(size_t)(j0 + jj) * HH + ks * 16 + kk];
    }
    __syncthreads();

    const int out_b  = tid >> 2;      // for tid<128: output this thread finalizes
    const int out_jj = tid & 3;

    for (int t = 0; t < TT; t++) {
        const float* hb = (t & 1) ? buf1 : buf0;
        float*       hn = (t & 1) ? buf0 : buf1;

        float preval = 0.0f;
        if (tid < 128)
            preval = pre[(size_t)t * (HH * BB) + (size_t)(j0 + out_jj) * BB + out_b];

        float4 acc[4];
#pragma unroll
        for (int a = 0; a < 4; a++) acc[a] = make_float4(0.f, 0.f, 0.f, 0.f);

        const float* hptr = hb + kseg * 16 * BB + b0;
#pragma unroll
        for (int kk = 0; kk < 16; kk++) {
            const float4 w = *(const float4*)&Wt[kk][kseg][0];
            const float4 h = __ldcg((const float4*)(hptr + kk * BB));
            acc[0].x += h.x * w.x; acc[0].y += h.x * w.y; acc[0].z += h.x * w.z; acc[0].w += h.x * w.w;
            acc[1].x += h.y * w.x; acc[1].y += h.y * w.y; acc[1].z += h.y * w.z; acc[1].w += h.y * w.w;
            acc[2].x += h.z * w.x; acc[2].y += h.z * w.y; acc[2].z += h.z * w.z; acc[2].w += h.z * w.w;
            acc[3].x += h.w * w.x; acc[3].y += h.w * w.y; acc[3].z += h.w * w.z; acc[3].w += h.w * w.w;
        }

        // dump partials: out index o = b*4 + jj, b = b0+bi
#pragma unroll
        for (int bi = 0; bi < 4; bi++)
            *(float4*)&ps[kseg][(b0 + bi) * 4] = acc[bi];
        __syncthreads();

        if (tid < 128) {
            float s0 = 0.f, s1 = 0.f, s2 = 0.f, s3 = 0.f;
#pragma unroll
            for (int ss = 0; ss < 32; ss += 4) {
                s0 += ps[ss + 0][tid];
                s1 += ps[ss + 1][tid];
                s2 += ps[ss + 2][tid];
                s3 += ps[ss + 3][tid];
            }
            const float val = tanhf(preval + (s0 + s1) + (s2 + s3));
            const int jdx = j0 + out_jj;
            hn[(size_t)jdx * BB + out_b] = val;
            traj[(size_t)t * (HH * BB) + (size_t)jdx * BB + out_b] = val;
        }

        __threadfence();
        __syncthreads();   // all stores + fences done; also guards ps reuse

        if (tid == 0) {
            unsigned arrived = atomicAdd(&counters[t], 1u) + 1u;
            if (arrived < 128u) {
                volatile unsigned* p = &counters[t];
                while (*p < 128u) { __nanosleep(40); }
            }
        }
        __syncthreads();
    }
}

// ---------------- transpose: g_tmp [T][O][B] -> out [B][O][T] ----------------
__global__ void transpose_kernel(const float* __restrict__ tmp, float* __restrict__ out)
{
    __shared__ float s[32][33];
    const int t0 = blockIdx.x * 32;
    const int o  = blockIdx.y;
    const int tx = threadIdx.x;   // 32
    const int ty = threadIdx.y;   // 8
#pragma unroll
    for (int i = 0; i < 4; i++) {
        int tt = t0 + ty + i * 8;
        s[ty + i * 8][tx] = tmp[(size_t)tt * (OO * BB) + (size_t)o * BB + tx];
    }
    __syncthreads();
#pragma unroll
    for (int i = 0; i < 4; i++) {
        int b = ty + i * 8;
        out[(size_t)b * (OO * TT) + (size_t)o * TT + t0 + tx] = s[tx][b];
    }
}

// ---------------- launch ----------------
extern "C" void kernel_launch(void* const* d_in, const int* in_sizes, int n_in,
                              void* d_out, int out_size)
{
    const float* inputs = (const float*)d_in[0];
    const float* W_ih0  = (const float*)d_in[1];
    const float* W_hh0  = (const float*)d_in[2];
    const float* b_ih0  = (const float*)d_in[3];
    const float* b_hh0  = (const float*)d_in[4];
    const float* W_ih1  = (const float*)d_in[5];
    const float* W_hh1  = (const float*)d_in[6];
    const float* b_ih1  = (const float*)d_in[7];
    const float* b_hh1  = (const float*)d_in[8];
    const float* W_fc   = (const float*)d_in[9];
    const float* b_fc   = (const float*)d_in[10];

    float *pre, *traj, *tmp, *hping;
    unsigned* counters;
    cudaGetSymbolAddress((void**)&pre,      g_pre);
    cudaGetSymbolAddress((void**)&traj,     g_traj);
    cudaGetSymbolAddress((void**)&tmp,      g_tmp);
    cudaGetSymbolAddress((void**)&hping,    g_hping);
    cudaGetSymbolAddress((void**)&counters, g_counters);

    init_kernel<<<64, 256>>>(counters, hping);

    // pre0[t][j][b] = inputs[b][t][:] . W_ih0[j][:] + b_ih0[j] + b_hh0[j]
    gemm_pre_kernel<<<dim3(4, TT / 2), 256>>>(inputs, W_ih0, b_ih0, b_hh0, pre,
                                              II, (long)II, 1L, (long)TT * II, HH);

    // layer 0 recurrence -> h1 trajectory
    rnn_layer_kernel<<<128, 256>>>(pre, traj, W_hh0,
                                   hping, hping + HH * BB, counters);

    // pre1[t][j][b] = h1[t][:][b] . W_ih1[j][:] + b_ih1[j] + b_hh1[j]
    gemm_pre_kernel<<<dim3(4, TT / 2), 256>>>(traj, W_ih1, b_ih1, b_hh1, pre,
                                              HH, (long)HH * BB, (long)BB, 1L, HH);

    // layer 1 recurrence -> h2 trajectory (reuses g_traj)
    rnn_layer_kernel<<<128, 256>>>(pre, traj, W_hh1,
                                   hping + 2 * HH * BB, hping + 3 * HH * BB,
                                   counters + 512);

    // fc: tmp[t][o][b] = h2[t][:][b] . W_fc[o][:] + b_fc[o]
    gemm_pre_kernel<<<dim3(1, TT / 2), 256>>>(traj, W_fc, b_fc, nullptr, tmp,
                                              HH, (long)HH * BB, (long)BB, 1L, OO);

    // out[b][o][t] = tmp[t][o][b]
    transpose_kernel<<<dim3(16, OO), dim3(32, 8)>>>(tmp, (float*)d_out);
}